// round 8
// baseline (speedup 1.0000x reference)
#include <cuda_runtime.h>
#include <cuda_bf16.h>
#include <math.h>
#include <stdint.h>

#define NN 170
#define NKP 192            // padded node dim (K of spatial GEMM, multiple of 32)
#define NROWP 192          // padded L rows (3 x 64 col tiles)
#define TT 12
#define BB 32
#define DD 120
#define HH 8
#define HD 15
#define FF 2048
#define BT (BB*TT)          // 384
#define MTOK (BB*TT*NN)     // 65280 = 510*128
#define MSP (BT*DD)         // 46080 = 360*128
#define XK 384              // padded xcat K (360 -> 384, multiple of 32)

#define FLAG_BIAS  1
#define FLAG_RELU  2
#define FLAG_T2    4        // epilogue: v = 2*acc - (Xh+Xl)

// ------------------------- static device scratch (zero-initialized) --------
__device__ float g_A[3*NN*NN];
__device__ float g_rs0[3*NN];
__device__ float g_rs1[3*NN];

__device__ __align__(16) __nv_bfloat16 g_Lh[3*NROWP*NKP];
__device__ __align__(16) __nv_bfloat16 g_Ll[3*NROWP*NKP];
__device__ __align__(16) __nv_bfloat16 g_xth[(size_t)MSP*NKP];
__device__ __align__(16) __nv_bfloat16 g_xtl[(size_t)MSP*NKP];
__device__ __align__(16) __nv_bfloat16 g_t1h[(size_t)MSP*NKP];
__device__ __align__(16) __nv_bfloat16 g_t1l[(size_t)MSP*NKP];
__device__ __align__(16) __nv_bfloat16 g_xcath[(size_t)3*MTOK*XK];  // per-branch!
__device__ __align__(16) __nv_bfloat16 g_xcatl[(size_t)3*MTOK*XK];
__device__ __align__(16) __nv_bfloat16 g_oah[(size_t)MTOK*128];
__device__ __align__(16) __nv_bfloat16 g_oal[(size_t)MTOK*128];
__device__ __align__(16) __nv_bfloat16 g_o1h[(size_t)MTOK*128];
__device__ __align__(16) __nv_bfloat16 g_o1l[(size_t)MTOK*128];
__device__ __align__(16) __nv_bfloat16 g_hidh[(size_t)MTOK*FF];
__device__ __align__(16) __nv_bfloat16 g_hidl[(size_t)MTOK*FF];
// B-operand weights, rows padded to tile boundary
__device__ __align__(16) __nv_bfloat16 g_wqh[3*128*XK];
__device__ __align__(16) __nv_bfloat16 g_wql[3*128*XK];
__device__ __align__(16) __nv_bfloat16 g_owh[128*128];
__device__ __align__(16) __nv_bfloat16 g_owl[128*128];
__device__ __align__(16) __nv_bfloat16 g_w1h[(size_t)FF*128];
__device__ __align__(16) __nv_bfloat16 g_w1l[(size_t)FF*128];
__device__ __align__(16) __nv_bfloat16 g_w2h[(size_t)128*FF];
__device__ __align__(16) __nv_bfloat16 g_w2l[(size_t)128*FF];
__device__ float g_qkv[(size_t)3*MTOK*DD];
__device__ float g_oproj[(size_t)MTOK*DD];
__device__ float g_out1f[(size_t)MTOK*DD];
__device__ float g_ffnf[(size_t)MTOK*DD];

// ------------------------- helpers -------------------------
__device__ __forceinline__ void bsplit(float v, __nv_bfloat16 &h, __nv_bfloat16 &l) {
    h = __float2bfloat16_rn(v);
    l = __float2bfloat16_rn(v - __bfloat162float(h));
}
__device__ __forceinline__ uint32_t smem_u32(const void* p) {
    uint32_t a;
    asm("{ .reg .u64 t; cvta.to.shared.u64 t, %1; cvt.u32.u64 %0, t; }" : "=r"(a) : "l"(p));
    return a;
}
__device__ __forceinline__ void ldm4(uint32_t (&d)[4], uint32_t addr) {
    asm volatile("ldmatrix.sync.aligned.m8n8.x4.shared.b16 {%0,%1,%2,%3}, [%4];"
                 : "=r"(d[0]), "=r"(d[1]), "=r"(d[2]), "=r"(d[3]) : "r"(addr));
}
__device__ __forceinline__ void mma16816(float (&c)[4], const uint32_t (&a)[4],
                                         uint32_t b0, uint32_t b1) {
    asm volatile("mma.sync.aligned.m16n8k16.row.col.f32.bf16.bf16.f32 "
                 "{%0,%1,%2,%3}, {%4,%5,%6,%7}, {%8,%9}, {%0,%1,%2,%3};"
                 : "+f"(c[0]), "+f"(c[1]), "+f"(c[2]), "+f"(c[3])
                 : "r"(a[0]), "r"(a[1]), "r"(a[2]), "r"(a[3]), "r"(b0), "r"(b1));
}

// ------------------------- HMMA bf16x3 GEMM (BK=32, double-buffered) -------
// D[M,N] = sum_k A[m,k]*B[n,k]; A: M x K (lda), B rows padded to tile bound (ldb).
// K%32==0, M%128==0.
// Batch mode (bstride!=0): br=blockIdx.y selects A/B/Cf/bias; col0=0.
// Else col0 = blockIdx.y*BN.
template<int BN>
__global__ __launch_bounds__(256) void hmma_bf16x3(
        const __nv_bfloat16* __restrict__ Ah, const __nv_bfloat16* __restrict__ Al, int lda,
        const __nv_bfloat16* __restrict__ Bh, const __nv_bfloat16* __restrict__ Bl, int ldb,
        int K,
        float* __restrict__ Cf, __nv_bfloat16* __restrict__ Ch, __nv_bfloat16* __restrict__ Cl,
        int ldc, int Nout,
        const float* __restrict__ bias, int flags,
        const __nv_bfloat16* __restrict__ Xh, const __nv_bfloat16* __restrict__ Xl,
        __nv_bfloat16* __restrict__ XCh, __nv_bfloat16* __restrict__ XCl, int xoff,
        long astride, long bstride, long cstride, int biasstride)
{
    constexpr int A80 = 128*5;              // 16B units per A matrix (80B row pitch)
    constexpr int B80 = BN*5;
    constexpr int STAGE_BYTES = (2*A80 + 2*B80) * 16;
    constexpr int NBA = 4;                  // A uint4 per thread
    constexpr int NBB = (BN*8)/256;         // B uint4 per thread
    constexpr int WN = BN / 2;
    constexpr int NP = WN / 16;

    extern __shared__ __align__(16) char smem[];
    const uint32_t sbase = smem_u32(smem);
    const int tid = threadIdx.x;
    const int lane = tid & 31;
    const int wid = tid >> 5;
    const int wm = wid & 3, wn = wid >> 2;
    const int row0 = blockIdx.x * 128;
    int col0;
    if (bstride != 0) {
        int br = blockIdx.y;
        col0 = 0;
        Ah += (size_t)br * astride;  Al += (size_t)br * astride;
        Bh += (size_t)br * bstride;  Bl += (size_t)br * bstride;
        if (Cf) Cf += (size_t)br * cstride;
        if (bias) bias += br * biasstride;
    } else {
        col0 = blockIdx.y * BN;
    }

    float acc[2][2*NP][4];
    #pragma unroll
    for (int i = 0; i < 2; i++)
        #pragma unroll
        for (int j = 0; j < 2*NP; j++)
            #pragma unroll
            for (int e = 0; e < 4; e++) acc[i][j][e] = 0.f;

    const int arow = wm*32 + (lane & 15);
    const uint32_t aoff = (uint32_t)arow*80 + ((lane >> 4) ? 16u : 0u);
    const int brow = wn*WN + (lane & 7) + ((lane >> 4) & 1)*8;
    const uint32_t boff = (uint32_t)(2*A80*16) + (uint32_t)brow*80 + (((lane >> 3) & 1) ? 16u : 0u);

    uint4 ra[NBA], rb[NBB];

    auto gload = [&](int c) {
        const int k0 = c * 32;
        #pragma unroll
        for (int t = 0; t < NBA; t++) {
            int i = tid + t*256;
            int mat = i >> 9, u = i & 511, r = u >> 2, kc = u & 3;
            ra[t] = *(const uint4*)((mat ? Al : Ah) + (size_t)(row0 + r)*lda + k0 + kc*8);
        }
        #pragma unroll
        for (int t = 0; t < NBB; t++) {
            int i = tid + t*256;
            int mat = i / (BN*4), u = i % (BN*4), r = u >> 2, kc = u & 3;
            rb[t] = *(const uint4*)((mat ? Bl : Bh) + (size_t)(col0 + r)*ldb + k0 + kc*8);
        }
    };
    auto sstore = [&](int st) {
        char* sb = smem + st * STAGE_BYTES;
        #pragma unroll
        for (int t = 0; t < NBA; t++) {
            int i = tid + t*256;
            int mat = i >> 9, u = i & 511, r = u >> 2, kc = u & 3;
            *(uint4*)(sb + mat*(A80*16) + r*80 + kc*16) = ra[t];
        }
        #pragma unroll
        for (int t = 0; t < NBB; t++) {
            int i = tid + t*256;
            int mat = i / (BN*4), u = i % (BN*4), r = u >> 2, kc = u & 3;
            *(uint4*)(sb + 2*(A80*16) + mat*(B80*16) + r*80 + kc*16) = rb[t];
        }
    };

    const int nch = K >> 5;
    gload(0);
    sstore(0);

    for (int c = 0; c < nch; c++) {
        if (c + 1 < nch) gload(c + 1);
        __syncthreads();

        const uint32_t sb = sbase + (uint32_t)(c & 1) * STAGE_BYTES;
        #pragma unroll
        for (int ks = 0; ks < 2; ks++) {
            uint32_t ahf[2][4], alf[2][4];
            #pragma unroll
            for (int mi = 0; mi < 2; mi++) {
                uint32_t ad = sb + aoff + ks*32 + (uint32_t)mi * (16*80);
                ldm4(ahf[mi], ad);
                ldm4(alf[mi], ad + A80*16);
            }
            uint32_t bhf[NP][4], blf[NP][4];
            #pragma unroll
            for (int np = 0; np < NP; np++) {
                uint32_t bd = sb + boff + ks*32 + (uint32_t)np * (16*80);
                ldm4(bhf[np], bd);
                ldm4(blf[np], bd + B80*16);
            }
            #pragma unroll
            for (int mi = 0; mi < 2; mi++)
                #pragma unroll
                for (int np = 0; np < NP; np++)
                    #pragma unroll
                    for (int hf = 0; hf < 2; hf++) {
                        int na = np*2 + hf;
                        mma16816(acc[mi][na], ahf[mi], bhf[np][2*hf], bhf[np][2*hf+1]);
                        mma16816(acc[mi][na], ahf[mi], blf[np][2*hf], blf[np][2*hf+1]);
                        mma16816(acc[mi][na], alf[mi], bhf[np][2*hf], bhf[np][2*hf+1]);
                    }
        }

        if (c + 1 < nch) sstore((c + 1) & 1);
    }

    // ---- epilogue
    float* smemf = (float*)smem;   // reuse as BN x 128 fp32 staging (pitch 132)
    if (XCh) __syncthreads();

    const int lr = lane >> 2, lc = (lane & 3) * 2;
    #pragma unroll
    for (int mi = 0; mi < 2; mi++) {
        #pragma unroll
        for (int na = 0; na < 2*NP; na++) {
            int gr0 = row0 + wm*32 + mi*16 + lr;
            int gc0l = wn*WN + na*8 + lc;
            #pragma unroll
            for (int e = 0; e < 4; e++) {
                int gr = gr0 + (e >> 1) * 8;
                int gcl = gc0l + (e & 1);
                int gc = col0 + gcl;
                if (gc >= Nout) continue;
                float v = acc[mi][na][e];
                size_t ci = (size_t)gr * ldc + gc;
                if (flags & FLAG_T2)
                    v = 2.f*v - (__bfloat162float(Xh[ci]) + __bfloat162float(Xl[ci]));
                if (flags & FLAG_BIAS) v += bias[gc];
                if (flags & FLAG_RELU) v = fmaxf(v, 0.f);
                if (Cf) Cf[ci] = v;
                if (Ch) { __nv_bfloat16 h, l; bsplit(v, h, l); Ch[ci] = h; Cl[ci] = l; }
                if (XCh) smemf[gcl*132 + (gr - row0)] = v;
            }
        }
    }

    if (XCh) {
        __syncthreads();
        for (int i = tid; i < BN*128; i += 256) {
            int gcl = i >> 7, grl = i & 127;
            int n = col0 + gcl;
            if (n >= Nout) continue;
            float v = smemf[gcl*132 + grl];
            int gr = row0 + grl;
            int bt = gr / DD, d = gr - bt*DD;
            __nv_bfloat16 h, l; bsplit(v, h, l);
            size_t idx = ((size_t)bt*NN + n)*XK + xoff + d;
            XCh[idx] = h; XCl[idx] = l;
        }
    }
}

// ------------------------- graph learning -------------------------
__global__ void gk1(const float* __restrict__ w1, const float* __restrict__ w2,
                    const float* __restrict__ beta, const float* __restrict__ cw,
                    const float* __restrict__ cb, const float* __restrict__ adj) {
    int r = blockIdx.x, br = blockIdx.y;
    __shared__ float w1r[DD], w2r[DD];
    __shared__ float red[256];
    const float* W1 = w1 + (size_t)br*NN*DD;
    const float* W2 = w2 + (size_t)br*NN*DD;
    for (int i = threadIdx.x; i < DD; i += blockDim.x) { w1r[i] = W1[r*DD+i]; w2r[i] = W2[r*DD+i]; }
    __syncthreads();
    float cw0 = cw[br*2+0], cw1 = cw[br*2+1], cbv = cb[br];
    float mysum = 0.f;
    for (int c = threadIdx.x; c < NN; c += blockDim.x) {
        const float* w1c = W1 + c*DD;
        const float* w2c = W2 + c*DD;
        float d1 = 0.f, d2 = 0.f;
        for (int e = 0; e < DD; e++) { d1 += w1r[e]*w2c[e]; d2 += w2r[e]*w1c[e]; }
        float nw = d1 - d2;
        if (r == c) nw += beta[br*NN + r];
        nw = fmaxf(nw, 0.f);
        float ad = adj[r*NN + c];
        float gate = 1.f / (1.f + expf(-(cw0*nw + cw1*ad + cbv)));
        float a = gate*nw + (1.f - gate)*ad;
        g_A[(size_t)br*NN*NN + (size_t)r*NN + c] = a;
        mysum += a;
    }
    red[threadIdx.x] = mysum; __syncthreads();
    for (int s = 128; s > 0; s >>= 1) { if (threadIdx.x < s) red[threadIdx.x] += red[threadIdx.x+s]; __syncthreads(); }
    if (threadIdx.x == 0) g_rs0[br*NN + r] = red[0];
}
__global__ void gk2() {
    int r = blockIdx.x, br = blockIdx.y;
    __shared__ float red[256];
    float dr = rsqrtf(g_rs0[br*NN + r]);
    const float eps = 0.5f / (float)NN;
    float mysum = 0.f;
    for (int c = threadIdx.x; c < NN; c += blockDim.x) {
        float dc = rsqrtf(g_rs0[br*NN + c]);
        size_t idx = (size_t)br*NN*NN + (size_t)r*NN + c;
        float a = fmaxf(dr * g_A[idx] * dc - eps, 0.f);
        g_A[idx] = a; mysum += a;
    }
    red[threadIdx.x] = mysum; __syncthreads();
    for (int s = 128; s > 0; s >>= 1) { if (threadIdx.x < s) red[threadIdx.x] += red[threadIdx.x+s]; __syncthreads(); }
    if (threadIdx.x == 0) g_rs1[br*NN + r] = red[0];
}
__global__ void gk3() {
    int r = blockIdx.x, br = blockIdx.y;
    __shared__ float red[256];
    float dr = rsqrtf(g_rs1[br*NN + r]);
    float mysum = 0.f;
    for (int c = threadIdx.x; c < NN; c += blockDim.x) {
        float dc = rsqrtf(g_rs1[br*NN + c]);
        size_t idx = (size_t)br*NN*NN + (size_t)r*NN + c;
        float g = dr * g_A[idx] * dc;
        g_A[idx] = g; mysum += g;
    }
    red[threadIdx.x] = mysum; __syncthreads();
    for (int s = 128; s > 0; s >>= 1) { if (threadIdx.x < s) red[threadIdx.x] += red[threadIdx.x+s]; __syncthreads(); }
    if (threadIdx.x == 0) g_rs0[br*NN + r] = red[0];
}
__global__ void gk4() {
    int r = blockIdx.x, br = blockIdx.y;
    float er = rsqrtf(g_rs0[br*NN + r]);
    for (int c = threadIdx.x; c < NKP; c += blockDim.x) {
        float L = 0.f;
        if (c < NN) {
            float ec = rsqrtf(g_rs0[br*NN + c]);
            L = ((r == c) ? 1.f : 0.f) - er * g_A[(size_t)br*NN*NN + (size_t)r*NN + c] * ec;
        }
        __nv_bfloat16 h, l; bsplit(L, h, l);
        size_t idx = (size_t)br*NROWP*NKP + (size_t)r*NKP + c;
        g_Lh[idx] = h; g_Ll[idx] = l;
    }
}

// ------------------------- layout / split kernels -------------------------
__global__ void xsplitT(const float* __restrict__ x) {
    __shared__ float s[64*121];
    int bt = blockIdx.x;
    for (int n0 = 0; n0 < NN; n0 += 64) {
        int nrows = (NN - n0 < 64) ? (NN - n0) : 64;
        for (int i = threadIdx.x; i < nrows*DD; i += 256) {
            int nn = i / DD, d = i - nn*DD;
            s[nn*121 + d] = x[((size_t)bt*NN + n0 + nn)*DD + d];
        }
        __syncthreads();
        for (int i = threadIdx.x; i < DD*64; i += 256) {
            int d = i >> 6, nn = i & 63;
            int n = n0 + nn;
            if (nn < nrows) {
                __nv_bfloat16 h, l; bsplit(s[nn*121 + d], h, l);
                size_t idx = ((size_t)bt*DD + d)*NKP + n;
                g_xth[idx] = h; g_xtl[idx] = l;
            }
        }
        __syncthreads();
    }
}
// write x into cols [0,120) of ALL THREE branch xcat buffers
__global__ void pack_x(const float* __restrict__ x) {
    size_t r = blockIdx.x;
    int d = threadIdx.x;
    if (d < DD) {
        __nv_bfloat16 h, l; bsplit(x[r*DD + d], h, l);
        #pragma unroll
        for (int br = 0; br < 3; br++) {
            size_t idx = (size_t)br*MTOK*XK + r*XK + d;
            g_xcath[idx] = h;
            g_xcatl[idx] = l;
        }
    }
}
__global__ void wsplit(const float* __restrict__ src, __nv_bfloat16* __restrict__ dh,
                       __nv_bfloat16* __restrict__ dl, int K, int N, int ldk,
                       long src_bstride, long dst_bstride) {
    int n = blockIdx.x;
    int br = blockIdx.y;
    src += (size_t)br * src_bstride;
    dh  += (size_t)br * dst_bstride;
    dl  += (size_t)br * dst_bstride;
    for (int k = threadIdx.x; k < K; k += blockDim.x) {
        __nv_bfloat16 h, l; bsplit(src[(size_t)k*N + n], h, l);
        dh[(size_t)n*ldk + k] = h;
        dl[(size_t)n*ldk + k] = l;
    }
}

// ------------------------- attention -------------------------
__global__ void attn_kernel(const float* __restrict__ qkv) {
    const float* q = qkv;
    const float* k = qkv + (size_t)MTOK*DD;
    const float* v = qkv + (size_t)2*MTOK*DD;
    int bn = blockIdx.x;
    int b = bn / NN, n = bn % NN;
    __shared__ float qs[TT][DD], ks[TT][DD], vs[TT][DD];
    for (int i = threadIdx.x; i < TT*DD; i += blockDim.x) {
        int t = i / DD, d = i % DD;
        size_t gi = (((size_t)(b*TT + t))*NN + n)*DD + d;
        qs[t][d] = q[gi]; ks[t][d] = k[gi]; vs[t][d] = v[gi];
    }
    __syncthreads();
    int tid = threadIdx.x;
    if (tid < HH*TT) {
        int h = tid / TT, qi = tid % TT;
        const float scale = rsqrtf((float)HD);
        float s[TT]; float mx = -1e30f;
        #pragma unroll
        for (int j = 0; j < TT; j++) {
            float acc = 0.f;
            #pragma unroll
            for (int e = 0; e < HD; e++) acc += qs[qi][h*HD+e] * ks[j][h*HD+e];
            acc *= scale; s[j] = acc; mx = fmaxf(mx, acc);
        }
        float sum = 0.f;
        #pragma unroll
        for (int j = 0; j < TT; j++) { s[j] = expf(s[j]-mx); sum += s[j]; }
        float inv = 1.f / sum;
        size_t orow = ((size_t)(b*TT + qi))*NN + n;
        #pragma unroll
        for (int e = 0; e < HD; e++) {
            float acc = 0.f;
            #pragma unroll
            for (int j = 0; j < TT; j++) acc += s[j] * vs[j][h*HD+e];
            __nv_bfloat16 hh, ll; bsplit(acc*inv, hh, ll);
            g_oah[orow*128 + h*HD + e] = hh;
            g_oal[orow*128 + h*HD + e] = ll;
        }
    }
}

// ------------------------- residual + layernorm -------------------------
__global__ void ln_kernel(const float* __restrict__ xa, const float* __restrict__ xb,
                          const float* __restrict__ gg, const float* __restrict__ bb,
                          float* __restrict__ outp, __nv_bfloat16* __restrict__ oh,
                          __nv_bfloat16* __restrict__ ol) {
    int warp = threadIdx.x >> 5, lane = threadIdx.x & 31;
    size_t m = (size_t)blockIdx.x * 4 + warp;
    if (m >= MTOK) return;
    size_t ia = m * DD;
    float v[4]; float s = 0.f;
    #pragma unroll
    for (int i = 0; i < 4; i++) {
        int d = lane + 32*i;
        float val = (d < DD) ? (xa[ia+d] + xb[ia+d]) : 0.f;
        v[i] = val; s += val;
    }
    #pragma unroll
    for (int o = 16; o > 0; o >>= 1) s += __shfl_xor_sync(0xffffffffu, s, o);
    float mean = s * (1.f / DD);
    float vsum = 0.f;
    #pragma unroll
    for (int i = 0; i < 4; i++) {
        int d = lane + 32*i;
        if (d < DD) { float df = v[i]-mean; vsum += df*df; }
    }
    #pragma unroll
    for (int o = 16; o > 0; o >>= 1) vsum += __shfl_xor_sync(0xffffffffu, vsum, o);
    float inv = rsqrtf(vsum * (1.f / DD) + 1e-5f);
    #pragma unroll
    for (int i = 0; i < 4; i++) {
        int d = lane + 32*i;
        if (d < DD) {
            float o = (v[i]-mean)*inv*gg[d] + bb[d];
            if (outp) outp[ia + d] = o;
            if (oh) { __nv_bfloat16 h, l; bsplit(o, h, l); oh[m*128 + d] = h; ol[m*128 + d] = l; }
        }
    }
}

// ------------------------- launch -------------------------
extern "C" void kernel_launch(void* const* d_in, const int* in_sizes, int n_in,
                              void* d_out, int out_size) {
    const float* x       = (const float*)d_in[0];
    const float* adj     = (const float*)d_in[1];
    const float* gl_beta = (const float*)d_in[2];
    const float* gl_w1   = (const float*)d_in[3];
    const float* gl_w2   = (const float*)d_in[4];
    const float* gl_cw   = (const float*)d_in[5];
    const float* gl_cb   = (const float*)d_in[6];
    const float* cheb_w  = (const float*)d_in[7];
    const float* cheb_b  = (const float*)d_in[8];
    const float* out_w   = (const float*)d_in[9];
    const float* out_b   = (const float*)d_in[10];
    const float* ff_w1   = (const float*)d_in[11];
    const float* ff_b1   = (const float*)d_in[12];
    const float* ff_w2   = (const float*)d_in[13];
    const float* ff_b2   = (const float*)d_in[14];
    const float* ln1_g   = (const float*)d_in[15];
    const float* ln1_b   = (const float*)d_in[16];
    const float* ln2_g   = (const float*)d_in[17];
    const float* ln2_b   = (const float*)d_in[18];
    float* outp = (float*)d_out;

    const int SMEM128 = 2 * (4*(128*5)) * 16;            // 81920
    const int SMEM64  = 2 * (2*(128*5) + 2*(64*5)) * 16; // 61440
    cudaFuncSetAttribute(hmma_bf16x3<128>, cudaFuncAttributeMaxDynamicSharedMemorySize, SMEM128);
    cudaFuncSetAttribute(hmma_bf16x3<64>,  cudaFuncAttributeMaxDynamicSharedMemorySize, SMEM64);

    __nv_bfloat16 *pLh, *pLl, *pxth, *pxtl, *pt1h, *pt1l;
    __nv_bfloat16 *pxch, *pxcl, *poah, *poal, *po1h, *po1l, *phh, *phl;
    __nv_bfloat16 *pwqh, *pwql, *powh, *powl, *pw1h, *pw1l, *pw2h, *pw2l;
    float *pqkv, *poproj, *pout1f, *pffnf;
    cudaGetSymbolAddress((void**)&pLh, g_Lh);   cudaGetSymbolAddress((void**)&pLl, g_Ll);
    cudaGetSymbolAddress((void**)&pxth, g_xth); cudaGetSymbolAddress((void**)&pxtl, g_xtl);
    cudaGetSymbolAddress((void**)&pt1h, g_t1h); cudaGetSymbolAddress((void**)&pt1l, g_t1l);
    cudaGetSymbolAddress((void**)&pxch, g_xcath); cudaGetSymbolAddress((void**)&pxcl, g_xcatl);
    cudaGetSymbolAddress((void**)&poah, g_oah); cudaGetSymbolAddress((void**)&poal, g_oal);
    cudaGetSymbolAddress((void**)&po1h, g_o1h); cudaGetSymbolAddress((void**)&po1l, g_o1l);
    cudaGetSymbolAddress((void**)&phh, g_hidh); cudaGetSymbolAddress((void**)&phl, g_hidl);
    cudaGetSymbolAddress((void**)&pwqh, g_wqh); cudaGetSymbolAddress((void**)&pwql, g_wql);
    cudaGetSymbolAddress((void**)&powh, g_owh); cudaGetSymbolAddress((void**)&powl, g_owl);
    cudaGetSymbolAddress((void**)&pw1h, g_w1h); cudaGetSymbolAddress((void**)&pw1l, g_w1l);
    cudaGetSymbolAddress((void**)&pw2h, g_w2h); cudaGetSymbolAddress((void**)&pw2l, g_w2l);
    cudaGetSymbolAddress((void**)&pqkv, g_qkv); cudaGetSymbolAddress((void**)&poproj, g_oproj);
    cudaGetSymbolAddress((void**)&pout1f, g_out1f); cudaGetSymbolAddress((void**)&pffnf, g_ffnf);

    // graph learning
    dim3 gG(NN, 3);
    gk1<<<gG, 256>>>(gl_w1, gl_w2, gl_beta, gl_cw, gl_cb, adj);
    gk2<<<gG, 256>>>();
    gk3<<<gG, 256>>>();
    gk4<<<gG, 256>>>();

    // layout + weight prep
    xsplitT<<<BT, 256>>>(x);
    pack_x<<<MTOK, 128>>>(x);
    wsplit<<<dim3(120,3), 256>>>(cheb_w, pwqh, pwql, 360, 120, XK, (long)360*120, (long)128*XK);
    wsplit<<<dim3(120,1), 256>>>(out_w, powh, powl, 120, 120, 128, 0, 0);
    wsplit<<<dim3(FF,1),  256>>>(ff_w1, pw1h, pw1l, 120, FF, 128, 0, 0);
    wsplit<<<dim3(120,1), 256>>>(ff_w2, pw2h, pw2l, FF, 120, FF, 0, 0);

    dim3 gsp(MSP/128, 3);    // spatial: BN=64, 3 col tiles
    dim3 gqkv(MTOK/128, 3);  // batched QKV: 3 branches
    dim3 gch(MTOK/128, 1);

    const long xcstride = (long)MTOK*XK;
    // per-branch: t1 = L @ x (t-layout + branch xcat[120..239]); t2 -> branch xcat[240..359]
    for (int i = 0; i < 3; i++) {
        const __nv_bfloat16* Lih = pLh + (size_t)i*NROWP*NKP;
        const __nv_bfloat16* Lil = pLl + (size_t)i*NROWP*NKP;
        __nv_bfloat16* xch_i = pxch + (size_t)i*xcstride;
        __nv_bfloat16* xcl_i = pxcl + (size_t)i*xcstride;
        hmma_bf16x3<64><<<gsp, 256, SMEM64>>>(pxth, pxtl, NKP, Lih, Lil, NKP, NKP,
                                              nullptr, pt1h, pt1l, NKP, NN,
                                              nullptr, 0, nullptr, nullptr,
                                              xch_i, xcl_i, 120, 0, 0, 0, 0);
        hmma_bf16x3<64><<<gsp, 256, SMEM64>>>(pt1h, pt1l, NKP, Lih, Lil, NKP, NKP,
                                              nullptr, nullptr, nullptr, NKP, NN,
                                              nullptr, FLAG_T2, pxth, pxtl,
                                              xch_i, xcl_i, 240, 0, 0, 0, 0);
    }
    // qkv (all 3 branches, one launch): relu(xcat_br @ W_br + b_br)
    hmma_bf16x3<128><<<gqkv, 256, SMEM128>>>(pxch, pxcl, XK, pwqh, pwql, XK, XK,
                                             pqkv, nullptr, nullptr, DD, DD,
                                             cheb_b, FLAG_BIAS | FLAG_RELU,
                                             nullptr, nullptr, nullptr, nullptr, 0,
                                             xcstride, (long)128*XK, (long)MTOK*DD, DD);

    attn_kernel<<<BB*NN, 128>>>(pqkv);

    // output projection
    hmma_bf16x3<128><<<gch, 256, SMEM128>>>(poah, poal, 128, powh, powl, 128, 128,
                                            poproj, nullptr, nullptr, DD, DD,
                                            out_b, FLAG_BIAS, nullptr, nullptr,
                                            nullptr, nullptr, 0, 0, 0, 0, 0);
    // LN1
    ln_kernel<<<MTOK/4, 128>>>(x, poproj, ln1_g, ln1_b, pout1f, po1h, po1l);

    // FFN1 -> bf16 h/l hidden
    dim3 gf1(MTOK/128, FF/128);
    hmma_bf16x3<128><<<gf1, 256, SMEM128>>>(po1h, po1l, 128, pw1h, pw1l, 128, 128,
                                            nullptr, phh, phl, FF, FF,
                                            ff_b1, FLAG_BIAS | FLAG_RELU, nullptr, nullptr,
                                            nullptr, nullptr, 0, 0, 0, 0, 0);
    // FFN2
    hmma_bf16x3<128><<<gch, 256, SMEM128>>>(phh, phl, FF, pw2h, pw2l, FF, FF,
                                            pffnf, nullptr, nullptr, DD, DD,
                                            ff_b2, FLAG_BIAS, nullptr, nullptr,
                                            nullptr, nullptr, 0, 0, 0, 0, 0);
    // LN2 -> output
    ln_kernel<<<MTOK/4, 128>>>(pout1f, pffnf, ln2_g, ln2_b, outp, nullptr, nullptr);
}

// round 9
// speedup vs baseline: 1.0399x; 1.0399x over previous
#include <cuda_runtime.h>
#include <cuda_bf16.h>
#include <math.h>
#include <stdint.h>

#define NN 170
#define NKP 176            // padded node dim (K of spatial GEMM, multiple of 16)
#define NROWP 192          // padded L rows (3 x 64 col tiles)
#define TT 12
#define BB 32
#define DD 120
#define HH 8
#define HD 15
#define FF 2048
#define BT (BB*TT)          // 384
#define MTOK (BB*TT*NN)     // 65280 = 510*128
#define MSP (BT*DD)         // 46080 = 360*128
#define XK 368              // padded xcat K (360 -> 368)

#define FLAG_BIAS  1
#define FLAG_RELU  2
#define FLAG_T2    4        // epilogue: v = 2*acc - (Xh+Xl)

// ------------------------- static device scratch (zero-initialized) --------
__device__ float g_A[3*NN*NN];
__device__ float g_rs0[3*NN];
__device__ float g_rs1[3*NN];

__device__ __align__(16) __nv_bfloat16 g_Lh[3*NROWP*NKP];
__device__ __align__(16) __nv_bfloat16 g_Ll[3*NROWP*NKP];
__device__ __align__(16) __nv_bfloat16 g_xth[(size_t)MSP*NKP];
__device__ __align__(16) __nv_bfloat16 g_xtl[(size_t)MSP*NKP];
__device__ __align__(16) __nv_bfloat16 g_t1h[(size_t)MSP*NKP];
__device__ __align__(16) __nv_bfloat16 g_t1l[(size_t)MSP*NKP];
__device__ __align__(16) __nv_bfloat16 g_xcath[(size_t)MTOK*XK];
__device__ __align__(16) __nv_bfloat16 g_xcatl[(size_t)MTOK*XK];
__device__ __align__(16) __nv_bfloat16 g_oah[(size_t)MTOK*128];
__device__ __align__(16) __nv_bfloat16 g_oal[(size_t)MTOK*128];
__device__ __align__(16) __nv_bfloat16 g_o1h[(size_t)MTOK*128];
__device__ __align__(16) __nv_bfloat16 g_o1l[(size_t)MTOK*128];
__device__ __align__(16) __nv_bfloat16 g_hidh[(size_t)MTOK*FF];
__device__ __align__(16) __nv_bfloat16 g_hidl[(size_t)MTOK*FF];
// B-operand weights, rows padded to tile boundary
__device__ __align__(16) __nv_bfloat16 g_wqh[3*128*XK];
__device__ __align__(16) __nv_bfloat16 g_wql[3*128*XK];
__device__ __align__(16) __nv_bfloat16 g_owh[128*128];
__device__ __align__(16) __nv_bfloat16 g_owl[128*128];
__device__ __align__(16) __nv_bfloat16 g_w1h[(size_t)FF*128];
__device__ __align__(16) __nv_bfloat16 g_w1l[(size_t)FF*128];
__device__ __align__(16) __nv_bfloat16 g_w2h[(size_t)128*FF];
__device__ __align__(16) __nv_bfloat16 g_w2l[(size_t)128*FF];
__device__ float g_q[(size_t)MTOK*DD];
__device__ float g_k[(size_t)MTOK*DD];
__device__ float g_v[(size_t)MTOK*DD];
__device__ float g_oproj[(size_t)MTOK*DD];
__device__ float g_out1f[(size_t)MTOK*DD];
__device__ float g_ffnf[(size_t)MTOK*DD];

// ------------------------- helpers -------------------------
__device__ __forceinline__ void bsplit(float v, __nv_bfloat16 &h, __nv_bfloat16 &l) {
    h = __float2bfloat16_rn(v);
    l = __float2bfloat16_rn(v - __bfloat162float(h));
}
__device__ __forceinline__ uint32_t smem_u32(const void* p) {
    uint32_t a;
    asm("{ .reg .u64 t; cvta.to.shared.u64 t, %1; cvt.u32.u64 %0, t; }" : "=r"(a) : "l"(p));
    return a;
}
__device__ __forceinline__ void cpa16(uint32_t dst, const void* src) {
    asm volatile("cp.async.cg.shared.global [%0], [%1], 16;"
                 :: "r"(dst), "l"(src) : "memory");
}
__device__ __forceinline__ void cp_commit() {
    asm volatile("cp.async.commit_group;" ::: "memory");
}
__device__ __forceinline__ void cp_wait0() {
    asm volatile("cp.async.wait_group 0;" ::: "memory");
}
__device__ __forceinline__ void ldm4(uint32_t (&d)[4], uint32_t addr) {
    asm volatile("ldmatrix.sync.aligned.m8n8.x4.shared.b16 {%0,%1,%2,%3}, [%4];"
                 : "=r"(d[0]), "=r"(d[1]), "=r"(d[2]), "=r"(d[3]) : "r"(addr));
}
__device__ __forceinline__ void mma16816(float (&c)[4], const uint32_t (&a)[4],
                                         uint32_t b0, uint32_t b1) {
    asm volatile("mma.sync.aligned.m16n8k16.row.col.f32.bf16.bf16.f32 "
                 "{%0,%1,%2,%3}, {%4,%5,%6,%7}, {%8,%9}, {%0,%1,%2,%3};"
                 : "+f"(c[0]), "+f"(c[1]), "+f"(c[2]), "+f"(c[3])
                 : "r"(a[0]), "r"(a[1]), "r"(a[2]), "r"(a[3]), "r"(b0), "r"(b1));
}

// ------------------------- HMMA bf16x3 GEMM (BK=16, cp.async 2-stage) -------
// D[M,N] = sum_k A[m,k]*B[n,k]; A: M x K (lda), B rows padded to tile bound (ldb).
// K%16==0, M%128==0. All global accesses unguarded (buffers padded), 16B aligned.
template<int BN>
__global__ __launch_bounds__(256, 2) void hmma_bf16x3(
        const __nv_bfloat16* __restrict__ Ah, const __nv_bfloat16* __restrict__ Al, int lda,
        const __nv_bfloat16* __restrict__ Bh, const __nv_bfloat16* __restrict__ Bl, int ldb,
        int K,
        float* __restrict__ Cf, __nv_bfloat16* __restrict__ Ch, __nv_bfloat16* __restrict__ Cl,
        int ldc, int Nout,
        const float* __restrict__ bias, int flags,
        const __nv_bfloat16* __restrict__ Xh, const __nv_bfloat16* __restrict__ Xl,
        __nv_bfloat16* __restrict__ XCh, __nv_bfloat16* __restrict__ XCl, int xoff)
{
    constexpr int A16 = 128*3;              // 16B units per A matrix (48B row pitch)
    constexpr int B16 = BN*3;
    constexpr int STAGE_BYTES = (2*A16 + 2*B16) * 16;
    constexpr int NB = (BN*4)/256;          // B 16B transfers per thread
    constexpr int WN = BN / 2;
    constexpr int NP = WN / 16;
    constexpr int BH = BN * 2;

    extern __shared__ __align__(16) char smem[];
    const uint32_t sbase = smem_u32(smem);
    const int tid = threadIdx.x;
    const int lane = tid & 31;
    const int wid = tid >> 5;
    const int wm = wid & 3, wn = wid >> 2;
    const int row0 = blockIdx.x * 128;
    const int col0 = blockIdx.y * BN;

    float acc[2][2*NP][4];
    #pragma unroll
    for (int i = 0; i < 2; i++)
        #pragma unroll
        for (int j = 0; j < 2*NP; j++)
            #pragma unroll
            for (int e = 0; e < 4; e++) acc[i][j][e] = 0.f;

    const int arow = wm*32 + (lane & 15);
    const int akc  = lane >> 4;
    const uint32_t aoff = (uint32_t)(arow*3 + akc) * 16;
    const int brow = wn*WN + (lane & 7) + ((lane >> 4) & 1)*8;
    const int bkc  = (lane >> 3) & 1;
    const uint32_t boff = (uint32_t)(2*A16 + brow*3 + bkc) * 16;

    // cp.async loader: chunk c into stage st (no register staging, no guards)
    auto cpload = [&](int c, int st) {
        const int k0 = c * 16;
        const uint32_t sb = sbase + (uint32_t)st * STAGE_BYTES;
        #pragma unroll
        for (int t = 0; t < 2; t++) {
            int i = tid + t*256;
            int mat = i >> 8, u = i & 255, r = u >> 1, kc = u & 1;
            cpa16(sb + (uint32_t)(mat*A16 + r*3 + kc)*16,
                  (mat ? Al : Ah) + (size_t)(row0 + r)*lda + k0 + kc*8);
        }
        #pragma unroll
        for (int t = 0; t < NB; t++) {
            int i = tid + t*256;
            int mat = i / BH, u = i % BH, r = u >> 1, kc = u & 1;
            cpa16(sb + (uint32_t)(2*A16 + mat*B16 + r*3 + kc)*16,
                  (mat ? Bl : Bh) + (size_t)(col0 + r)*ldb + k0 + kc*8);
        }
        cp_commit();
    };

    const int nch = K >> 4;
    cpload(0, 0);

    for (int c = 0; c < nch; c++) {
        cp_wait0();                      // stage (c&1) data arrived
        __syncthreads();                 // visible to all; prev compute done
        if (c + 1 < nch) cpload(c + 1, (c + 1) & 1);

        const uint32_t sb = sbase + (uint32_t)(c & 1) * STAGE_BYTES;
        uint32_t ahf[2][4], alf[2][4];
        #pragma unroll
        for (int mi = 0; mi < 2; mi++) {
            uint32_t ad = sb + aoff + (uint32_t)mi * 768;
            ldm4(ahf[mi], ad);
            ldm4(alf[mi], ad + A16*16);
        }
        uint32_t bhf[NP][4], blf[NP][4];
        #pragma unroll
        for (int np = 0; np < NP; np++) {
            uint32_t bd = sb + boff + (uint32_t)np * 768;
            ldm4(bhf[np], bd);
            ldm4(blf[np], bd + B16*16);
        }
        #pragma unroll
        for (int mi = 0; mi < 2; mi++)
            #pragma unroll
            for (int np = 0; np < NP; np++)
                #pragma unroll
                for (int hf = 0; hf < 2; hf++) {
                    int na = np*2 + hf;
                    mma16816(acc[mi][na], ahf[mi], bhf[np][2*hf], bhf[np][2*hf+1]);
                    mma16816(acc[mi][na], ahf[mi], blf[np][2*hf], blf[np][2*hf+1]);
                    mma16816(acc[mi][na], alf[mi], bhf[np][2*hf], bhf[np][2*hf+1]);
                }
        __syncthreads();                 // done reading stage (c&1) before next overwrite
    }

    // ---- epilogue
    float* smemf = (float*)smem;   // reuse as BN x 128 fp32 staging (pitch 132)

    const int lr = lane >> 2, lc = (lane & 3) * 2;
    #pragma unroll
    for (int mi = 0; mi < 2; mi++) {
        #pragma unroll
        for (int na = 0; na < 2*NP; na++) {
            int gr0 = row0 + wm*32 + mi*16 + lr;
            int gc0l = wn*WN + na*8 + lc;
            #pragma unroll
            for (int e = 0; e < 4; e++) {
                int gr = gr0 + (e >> 1) * 8;
                int gcl = gc0l + (e & 1);
                int gc = col0 + gcl;
                if (gc >= Nout) continue;
                float v = acc[mi][na][e];
                size_t ci = (size_t)gr * ldc + gc;
                if (flags & FLAG_T2)
                    v = 2.f*v - (__bfloat162float(Xh[ci]) + __bfloat162float(Xl[ci]));
                if (flags & FLAG_BIAS) v += bias[gc];
                if (flags & FLAG_RELU) v = fmaxf(v, 0.f);
                if (Cf) Cf[ci] = v;
                if (Ch) { __nv_bfloat16 h, l; bsplit(v, h, l); Ch[ci] = h; Cl[ci] = l; }
                if (XCh) smemf[gcl*132 + (gr - row0)] = v;
            }
        }
    }

    if (XCh) {
        __syncthreads();
        for (int i = tid; i < BN*128; i += 256) {
            int gcl = i >> 7, grl = i & 127;
            int n = col0 + gcl;
            if (n >= Nout) continue;
            float v = smemf[gcl*132 + grl];
            int gr = row0 + grl;
            int bt = gr / DD, d = gr - bt*DD;
            __nv_bfloat16 h, l; bsplit(v, h, l);
            size_t idx = ((size_t)bt*NN + n)*XK + xoff + d;
            XCh[idx] = h; XCl[idx] = l;
        }
    }
}

// ------------------------- graph learning -------------------------
__global__ void gk1(const float* __restrict__ w1, const float* __restrict__ w2,
                    const float* __restrict__ beta, const float* __restrict__ cw,
                    const float* __restrict__ cb, const float* __restrict__ adj) {
    int r = blockIdx.x, br = blockIdx.y;
    __shared__ float w1r[DD], w2r[DD];
    __shared__ float red[256];
    const float* W1 = w1 + (size_t)br*NN*DD;
    const float* W2 = w2 + (size_t)br*NN*DD;
    for (int i = threadIdx.x; i < DD; i += blockDim.x) { w1r[i] = W1[r*DD+i]; w2r[i] = W2[r*DD+i]; }
    __syncthreads();
    float cw0 = cw[br*2+0], cw1 = cw[br*2+1], cbv = cb[br];
    float mysum = 0.f;
    for (int c = threadIdx.x; c < NN; c += blockDim.x) {
        const float* w1c = W1 + c*DD;
        const float* w2c = W2 + c*DD;
        float d1 = 0.f, d2 = 0.f;
        for (int e = 0; e < DD; e++) { d1 += w1r[e]*w2c[e]; d2 += w2r[e]*w1c[e]; }
        float nw = d1 - d2;
        if (r == c) nw += beta[br*NN + r];
        nw = fmaxf(nw, 0.f);
        float ad = adj[r*NN + c];
        float gate = 1.f / (1.f + expf(-(cw0*nw + cw1*ad + cbv)));
        float a = gate*nw + (1.f - gate)*ad;
        g_A[(size_t)br*NN*NN + (size_t)r*NN + c] = a;
        mysum += a;
    }
    red[threadIdx.x] = mysum; __syncthreads();
    for (int s = 128; s > 0; s >>= 1) { if (threadIdx.x < s) red[threadIdx.x] += red[threadIdx.x+s]; __syncthreads(); }
    if (threadIdx.x == 0) g_rs0[br*NN + r] = red[0];
}
__global__ void gk2() {
    int r = blockIdx.x, br = blockIdx.y;
    __shared__ float red[256];
    float dr = rsqrtf(g_rs0[br*NN + r]);
    const float eps = 0.5f / (float)NN;
    float mysum = 0.f;
    for (int c = threadIdx.x; c < NN; c += blockDim.x) {
        float dc = rsqrtf(g_rs0[br*NN + c]);
        size_t idx = (size_t)br*NN*NN + (size_t)r*NN + c;
        float a = fmaxf(dr * g_A[idx] * dc - eps, 0.f);
        g_A[idx] = a; mysum += a;
    }
    red[threadIdx.x] = mysum; __syncthreads();
    for (int s = 128; s > 0; s >>= 1) { if (threadIdx.x < s) red[threadIdx.x] += red[threadIdx.x+s]; __syncthreads(); }
    if (threadIdx.x == 0) g_rs1[br*NN + r] = red[0];
}
__global__ void gk3() {
    int r = blockIdx.x, br = blockIdx.y;
    __shared__ float red[256];
    float dr = rsqrtf(g_rs1[br*NN + r]);
    float mysum = 0.f;
    for (int c = threadIdx.x; c < NN; c += blockDim.x) {
        float dc = rsqrtf(g_rs1[br*NN + c]);
        size_t idx = (size_t)br*NN*NN + (size_t)r*NN + c;
        float g = dr * g_A[idx] * dc;
        g_A[idx] = g; mysum += g;
    }
    red[threadIdx.x] = mysum; __syncthreads();
    for (int s = 128; s > 0; s >>= 1) { if (threadIdx.x < s) red[threadIdx.x] += red[threadIdx.x+s]; __syncthreads(); }
    if (threadIdx.x == 0) g_rs0[br*NN + r] = red[0];
}
__global__ void gk4() {
    int r = blockIdx.x, br = blockIdx.y;
    float er = rsqrtf(g_rs0[br*NN + r]);
    for (int c = threadIdx.x; c < NKP; c += blockDim.x) {
        float L = 0.f;
        if (c < NN) {
            float ec = rsqrtf(g_rs0[br*NN + c]);
            L = ((r == c) ? 1.f : 0.f) - er * g_A[(size_t)br*NN*NN + (size_t)r*NN + c] * ec;
        }
        __nv_bfloat16 h, l; bsplit(L, h, l);
        size_t idx = (size_t)br*NROWP*NKP + (size_t)r*NKP + c;
        g_Lh[idx] = h; g_Ll[idx] = l;
    }
}

// ------------------------- layout / split kernels -------------------------
__global__ void xsplitT(const float* __restrict__ x) {
    __shared__ float s[64*121];
    int bt = blockIdx.x;
    for (int n0 = 0; n0 < NN; n0 += 64) {
        int nrows = (NN - n0 < 64) ? (NN - n0) : 64;
        for (int i = threadIdx.x; i < nrows*DD; i += 256) {
            int nn = i / DD, d = i - nn*DD;
            s[nn*121 + d] = x[((size_t)bt*NN + n0 + nn)*DD + d];
        }
        __syncthreads();
        for (int i = threadIdx.x; i < DD*64; i += 256) {
            int d = i >> 6, nn = i & 63;
            int n = n0 + nn;
            if (nn < nrows) {
                __nv_bfloat16 h, l; bsplit(s[nn*121 + d], h, l);
                size_t idx = ((size_t)bt*DD + d)*NKP + n;
                g_xth[idx] = h; g_xtl[idx] = l;
            }
        }
        __syncthreads();
    }
}
__global__ void pack_x(const float* __restrict__ x) {
    size_t r = blockIdx.x;
    int d = threadIdx.x;
    if (d < DD) {
        __nv_bfloat16 h, l; bsplit(x[r*DD + d], h, l);
        g_xcath[r*XK + d] = h;
        g_xcatl[r*XK + d] = l;
    }
}
__global__ void wsplit(const float* __restrict__ src, __nv_bfloat16* __restrict__ dh,
                       __nv_bfloat16* __restrict__ dl, int K, int N, int ldk,
                       long src_bstride, long dst_bstride) {
    int n = blockIdx.x;
    int br = blockIdx.y;
    src += (size_t)br * src_bstride;
    dh  += (size_t)br * dst_bstride;
    dl  += (size_t)br * dst_bstride;
    for (int k = threadIdx.x; k < K; k += blockDim.x) {
        __nv_bfloat16 h, l; bsplit(src[(size_t)k*N + n], h, l);
        dh[(size_t)n*ldk + k] = h;
        dl[(size_t)n*ldk + k] = l;
    }
}

// ------------------------- attention -------------------------
__global__ void attn_kernel(const float* __restrict__ q, const float* __restrict__ k,
                            const float* __restrict__ v) {
    int bn = blockIdx.x;
    int b = bn / NN, n = bn % NN;
    __shared__ float qs[TT][DD], ks[TT][DD], vs[TT][DD];
    for (int i = threadIdx.x; i < TT*DD; i += blockDim.x) {
        int t = i / DD, d = i % DD;
        size_t gi = (((size_t)(b*TT + t))*NN + n)*DD + d;
        qs[t][d] = q[gi]; ks[t][d] = k[gi]; vs[t][d] = v[gi];
    }
    __syncthreads();
    int tid = threadIdx.x;
    if (tid < HH*TT) {
        int h = tid / TT, qi = tid % TT;
        const float scale = rsqrtf((float)HD);
        float s[TT]; float mx = -1e30f;
        #pragma unroll
        for (int j = 0; j < TT; j++) {
            float acc = 0.f;
            #pragma unroll
            for (int e = 0; e < HD; e++) acc += qs[qi][h*HD+e] * ks[j][h*HD+e];
            acc *= scale; s[j] = acc; mx = fmaxf(mx, acc);
        }
        float sum = 0.f;
        #pragma unroll
        for (int j = 0; j < TT; j++) { s[j] = expf(s[j]-mx); sum += s[j]; }
        float inv = 1.f / sum;
        size_t orow = ((size_t)(b*TT + qi))*NN + n;
        #pragma unroll
        for (int e = 0; e < HD; e++) {
            float acc = 0.f;
            #pragma unroll
            for (int j = 0; j < TT; j++) acc += s[j] * vs[j][h*HD+e];
            __nv_bfloat16 hh, ll; bsplit(acc*inv, hh, ll);
            g_oah[orow*128 + h*HD + e] = hh;
            g_oal[orow*128 + h*HD + e] = ll;
        }
    }
}

// ------------------------- residual + layernorm -------------------------
__global__ void ln_kernel(const float* __restrict__ xa, const float* __restrict__ xb,
                          const float* __restrict__ gg, const float* __restrict__ bb,
                          float* __restrict__ outp, __nv_bfloat16* __restrict__ oh,
                          __nv_bfloat16* __restrict__ ol) {
    int warp = threadIdx.x >> 5, lane = threadIdx.x & 31;
    size_t m = (size_t)blockIdx.x * 4 + warp;
    if (m >= MTOK) return;
    size_t ia = m * DD;
    float v[4]; float s = 0.f;
    #pragma unroll
    for (int i = 0; i < 4; i++) {
        int d = lane + 32*i;
        float val = (d < DD) ? (xa[ia+d] + xb[ia+d]) : 0.f;
        v[i] = val; s += val;
    }
    #pragma unroll
    for (int o = 16; o > 0; o >>= 1) s += __shfl_xor_sync(0xffffffffu, s, o);
    float mean = s * (1.f / DD);
    float vsum = 0.f;
    #pragma unroll
    for (int i = 0; i < 4; i++) {
        int d = lane + 32*i;
        if (d < DD) { float df = v[i]-mean; vsum += df*df; }
    }
    #pragma unroll
    for (int o = 16; o > 0; o >>= 1) vsum += __shfl_xor_sync(0xffffffffu, vsum, o);
    float inv = rsqrtf(vsum * (1.f / DD) + 1e-5f);
    #pragma unroll
    for (int i = 0; i < 4; i++) {
        int d = lane + 32*i;
        if (d < DD) {
            float o = (v[i]-mean)*inv*gg[d] + bb[d];
            if (outp) outp[ia + d] = o;
            if (oh) { __nv_bfloat16 h, l; bsplit(o, h, l); oh[m*128 + d] = h; ol[m*128 + d] = l; }
        }
    }
}

// ------------------------- launch -------------------------
extern "C" void kernel_launch(void* const* d_in, const int* in_sizes, int n_in,
                              void* d_out, int out_size) {
    const float* x       = (const float*)d_in[0];
    const float* adj     = (const float*)d_in[1];
    const float* gl_beta = (const float*)d_in[2];
    const float* gl_w1   = (const float*)d_in[3];
    const float* gl_w2   = (const float*)d_in[4];
    const float* gl_cw   = (const float*)d_in[5];
    const float* gl_cb   = (const float*)d_in[6];
    const float* cheb_w  = (const float*)d_in[7];
    const float* cheb_b  = (const float*)d_in[8];
    const float* out_w   = (const float*)d_in[9];
    const float* out_b   = (const float*)d_in[10];
    const float* ff_w1   = (const float*)d_in[11];
    const float* ff_b1   = (const float*)d_in[12];
    const float* ff_w2   = (const float*)d_in[13];
    const float* ff_b2   = (const float*)d_in[14];
    const float* ln1_g   = (const float*)d_in[15];
    const float* ln1_b   = (const float*)d_in[16];
    const float* ln2_g   = (const float*)d_in[17];
    const float* ln2_b   = (const float*)d_in[18];
    float* outp = (float*)d_out;

    const int SMEM128 = 2 * (2*(128*3) + 2*(128*3)) * 16;   // 49152
    const int SMEM64  = 2 * (2*(128*3) + 2*(64*3)) * 16;    // 36864
    cudaFuncSetAttribute(hmma_bf16x3<128>, cudaFuncAttributeMaxDynamicSharedMemorySize, SMEM128);
    cudaFuncSetAttribute(hmma_bf16x3<64>,  cudaFuncAttributeMaxDynamicSharedMemorySize, SMEM64);

    __nv_bfloat16 *pLh, *pLl, *pxth, *pxtl, *pt1h, *pt1l;
    __nv_bfloat16 *pxch, *pxcl, *poah, *poal, *po1h, *po1l, *phh, *phl;
    __nv_bfloat16 *pwqh, *pwql, *powh, *powl, *pw1h, *pw1l, *pw2h, *pw2l;
    float *pq, *pk, *pv, *poproj, *pout1f, *pffnf;
    cudaGetSymbolAddress((void**)&pLh, g_Lh);   cudaGetSymbolAddress((void**)&pLl, g_Ll);
    cudaGetSymbolAddress((void**)&pxth, g_xth); cudaGetSymbolAddress((void**)&pxtl, g_xtl);
    cudaGetSymbolAddress((void**)&pt1h, g_t1h); cudaGetSymbolAddress((void**)&pt1l, g_t1l);
    cudaGetSymbolAddress((void**)&pxch, g_xcath); cudaGetSymbolAddress((void**)&pxcl, g_xcatl);
    cudaGetSymbolAddress((void**)&poah, g_oah); cudaGetSymbolAddress((void**)&poal, g_oal);
    cudaGetSymbolAddress((void**)&po1h, g_o1h); cudaGetSymbolAddress((void**)&po1l, g_o1l);
    cudaGetSymbolAddress((void**)&phh, g_hidh); cudaGetSymbolAddress((void**)&phl, g_hidl);
    cudaGetSymbolAddress((void**)&pwqh, g_wqh); cudaGetSymbolAddress((void**)&pwql, g_wql);
    cudaGetSymbolAddress((void**)&powh, g_owh); cudaGetSymbolAddress((void**)&powl, g_owl);
    cudaGetSymbolAddress((void**)&pw1h, g_w1h); cudaGetSymbolAddress((void**)&pw1l, g_w1l);
    cudaGetSymbolAddress((void**)&pw2h, g_w2h); cudaGetSymbolAddress((void**)&pw2l, g_w2l);
    cudaGetSymbolAddress((void**)&pq, g_q);     cudaGetSymbolAddress((void**)&pk, g_k);
    cudaGetSymbolAddress((void**)&pv, g_v);     cudaGetSymbolAddress((void**)&poproj, g_oproj);
    cudaGetSymbolAddress((void**)&pout1f, g_out1f); cudaGetSymbolAddress((void**)&pffnf, g_ffnf);

    // graph learning
    dim3 gG(NN, 3);
    gk1<<<gG, 256>>>(gl_w1, gl_w2, gl_beta, gl_cw, gl_cb, adj);
    gk2<<<gG, 256>>>();
    gk3<<<gG, 256>>>();
    gk4<<<gG, 256>>>();

    // layout + weight prep
    xsplitT<<<BT, 256>>>(x);
    pack_x<<<MTOK, 128>>>(x);
    wsplit<<<dim3(120,3), 256>>>(cheb_w, pwqh, pwql, 360, 120, XK, (long)360*120, (long)128*XK);
    wsplit<<<dim3(120,1), 256>>>(out_w, powh, powl, 120, 120, 128, 0, 0);
    wsplit<<<dim3(FF,1),  256>>>(ff_w1, pw1h, pw1l, 120, FF, 128, 0, 0);
    wsplit<<<dim3(120,1), 256>>>(ff_w2, pw2h, pw2l, FF, 120, FF, 0, 0);

    float* qkv[3] = {pq, pk, pv};
    dim3 gsp(MSP/128, 3);   // spatial: BN=64, 3 col tiles
    dim3 gch(MTOK/128, 1);  // channel: BN=128

    for (int i = 0; i < 3; i++) {
        const __nv_bfloat16* Lih = pLh + (size_t)i*NROWP*NKP;
        const __nv_bfloat16* Lil = pLl + (size_t)i*NROWP*NKP;
        // t1 = L @ x : write t-layout (for T2 chain) + xcat[120..239]
        hmma_bf16x3<64><<<gsp, 256, SMEM64>>>(pxth, pxtl, NKP, Lih, Lil, NKP, NKP,
                                              nullptr, pt1h, pt1l, NKP, NN,
                                              nullptr, 0, nullptr, nullptr,
                                              pxch, pxcl, 120);
        // t2 = 2*(L @ t1) - x : write xcat[240..359] only
        hmma_bf16x3<64><<<gsp, 256, SMEM64>>>(pt1h, pt1l, NKP, Lih, Lil, NKP, NKP,
                                              nullptr, nullptr, nullptr, NKP, NN,
                                              nullptr, FLAG_T2, pxth, pxtl,
                                              pxch, pxcl, 240);
        // qkv_i = relu(xcat @ W_i + b_i), K=368
        hmma_bf16x3<128><<<gch, 256, SMEM128>>>(pxch, pxcl, XK,
                                                pwqh + (size_t)i*128*XK, pwql + (size_t)i*128*XK,
                                                XK, XK,
                                                qkv[i], nullptr, nullptr, DD, DD,
                                                cheb_b + (size_t)i*DD, FLAG_BIAS | FLAG_RELU,
                                                nullptr, nullptr, nullptr, nullptr, 0);
    }

    attn_kernel<<<BB*NN, 128>>>(pq, pk, pv);

    // output projection
    hmma_bf16x3<128><<<gch, 256, SMEM128>>>(poah, poal, 128, powh, powl, 128, 128,
                                            poproj, nullptr, nullptr, DD, DD,
                                            out_b, FLAG_BIAS, nullptr, nullptr,
                                            nullptr, nullptr, 0);
    // LN1
    ln_kernel<<<MTOK/4, 128>>>(x, poproj, ln1_g, ln1_b, pout1f, po1h, po1l);

    // FFN1 -> bf16 h/l hidden
    dim3 gf1(MTOK/128, FF/128);
    hmma_bf16x3<128><<<gf1, 256, SMEM128>>>(po1h, po1l, 128, pw1h, pw1l, 128, 128,
                                            nullptr, phh, phl, FF, FF,
                                            ff_b1, FLAG_BIAS | FLAG_RELU, nullptr, nullptr,
                                            nullptr, nullptr, 0);
    // FFN2
    hmma_bf16x3<128><<<gch, 256, SMEM128>>>(phh, phl, FF, pw2h, pw2l, FF, FF,
                                            pffnf, nullptr, nullptr, DD, DD,
                                            ff_b2, FLAG_BIAS, nullptr, nullptr,
                                            nullptr, nullptr, 0);
    // LN2 -> output
    ln_kernel<<<MTOK/4, 128>>>(pout1f, pffnf, ln2_g, ln2_b, outp, nullptr, nullptr);
}